// round 4
// baseline (speedup 1.0000x reference)
#include <cuda_runtime.h>
#include <cuda_bf16.h>
#include <cstdint>

#define MAXN 50000
#define MAXE 800000
#define Hd   64
#define MAXK 16

// ---------------- device scratch (no allocs allowed) ----------------
static __device__ float g_agg1[(size_t)MAXN * Hd];  // layer-1 aggregation
static __device__ float g_h1[(size_t)MAXN * Hd];    // relu(conv1 mlp output)
static __device__ int   g_is64;                     // index dtype flag
static __device__ int   g_targets[2 + MAXK];        // [curr, dest, nbr0..15]
static __device__ float g_agg2[(2 + MAXK) * Hd];    // layer-2 aggregation at targets
static __device__ int   g_elist[MAXE];              // edges with dst in targets
static __device__ int   g_ecount;

#define FMA_F32X2(d, a, b, c) \
    asm("fma.rn.f32x2 %0, %1, %2, %3;" : "=l"(d) : "l"(a), "l"(b), "l"(c))
#define PACK_DUP_F32X2(out, v) \
    asm("mov.b64 %0, {%1, %1};" : "=l"(out) : "r"(__float_as_uint(v)))

// ---------------- prep: zero agg1 grid-wide; block 0 does detect/targets ----
__global__ void k_prep(const void* ei, int E, long long N,
                       const void* curr, const void* dest, const void* nbr, int K) {
    int i = blockIdx.x * blockDim.x + threadIdx.x;
    int n4 = (int)((N * Hd) / 4);
    if (i < n4) ((float4*)g_agg1)[i] = make_float4(0.f, 0.f, 0.f, 0.f);

    if (blockIdx.x == 0) {
        __shared__ int s_is64;
        if (threadIdx.x == 0) {
            const long long* p = (const long long*)ei;
            int n = E < 8 ? E : 8;
            int ok = 1;
            for (int q = 0; q < n; q++) {
                long long v = p[q];
                if (v < 0 || v >= N) { ok = 0; break; }
            }
            g_is64 = ok;
            s_is64 = ok;
            g_ecount = 0;
        }
        __syncthreads();
        int is64 = s_is64;
        int t = threadIdx.x;
        if (t == 0) g_targets[0] = is64 ? (int)((const long long*)curr)[0] : ((const int*)curr)[0];
        if (t == 1) g_targets[1] = is64 ? (int)((const long long*)dest)[0] : ((const int*)dest)[0];
        if (t >= 2 && t < 2 + K)
            g_targets[t] = is64 ? (int)((const long long*)nbr)[t - 2] : ((const int*)nbr)[t - 2];
        if (t >= 2 + K && t < 2 + MAXK) g_targets[t] = -1;
        for (int q = t; q < (2 + MAXK) * Hd; q += blockDim.x) g_agg2[q] = 0.f;
    }
}

// ---------------- edge pass 1: full scatter-add + target filter ------------
__global__ void k_edge1(const float* __restrict__ x, const void* __restrict__ ei,
                        const float* __restrict__ ea, const float* __restrict__ We1,
                        const float* __restrict__ be1, int E) {
    __shared__ int tg[2 + MAXK];
    if (threadIdx.x < 2 + MAXK) tg[threadIdx.x] = g_targets[threadIdx.x];
    __syncthreads();

    int gid = blockIdx.x * blockDim.x + threadIdx.x;
    int e = gid >> 4;
    if (e >= E) return;
    int l = gid & 15;

    long long s, d;
    if (g_is64) {
        const long long* p = (const long long*)ei;
        s = __ldg(&p[e]); d = __ldg(&p[E + e]);
    } else {
        const int* p = (const int*)ei;
        s = (long long)__ldg(&p[e]); d = (long long)__ldg(&p[E + e]);
    }
    float a = __ldg(&ea[e]);

    if (l == 0) {   // free filtering for edge pass 2
        int di = (int)d;
        bool match = false;
        #pragma unroll
        for (int t = 0; t < 2 + MAXK; t++) match |= (di == tg[t]);
        if (match) {
            int pos = atomicAdd(&g_ecount, 1);
            g_elist[pos] = e;   // capacity = E, cannot overflow
        }
    }

    float4 xv = __ldg((const float4*)(x + s * Hd) + l);
    float4 wv = __ldg((const float4*)We1 + l);
    float4 bv = __ldg((const float4*)be1 + l);

    float4 m;
    m.x = fmaxf(xv.x + fmaf(a, wv.x, bv.x), 0.f);
    m.y = fmaxf(xv.y + fmaf(a, wv.y, bv.y), 0.f);
    m.z = fmaxf(xv.z + fmaf(a, wv.z, bv.z), 0.f);
    m.w = fmaxf(xv.w + fmaf(a, wv.w, bv.w), 0.f);

    float* dp = g_agg1 + d * Hd + l * 4;
    asm volatile("red.global.add.v4.f32 [%0], {%1,%2,%3,%4};"
                 :: "l"(dp), "f"(m.x), "f"(m.y), "f"(m.z), "f"(m.w)
                 : "memory");
}

// ---------------- node MLP for layer 1 (round-1 tiling + FFMA2) ------------
// 32 nodes / block, 128 threads, two 64x64 GEMMs, 4x4 microtile via f32x2.
#define NT 32
__global__ void __launch_bounds__(128) k_mlp1(
        const float* __restrict__ x,
        const float* __restrict__ Wa, const float* __restrict__ ba,
        const float* __restrict__ Wb, const float* __restrict__ bb, int N) {
    __shared__ float sWa[Hd * Hd];
    __shared__ float sWb[Hd * Hd];
    __shared__ float sba[Hd], sbb[Hd];
    __shared__ float T[Hd * NT];   // [k][n] transposed node tile (reused as U)

    int tid = threadIdx.x;
    for (int i = tid * 4; i < Hd * Hd; i += 128 * 4) {
        *(float4*)&sWa[i] = *(const float4*)&Wa[i];
        *(float4*)&sWb[i] = *(const float4*)&Wb[i];
    }
    if (tid < Hd) { sba[tid] = ba[tid]; sbb[tid] = bb[tid]; }

    long long n0 = (long long)blockIdx.x * NT;
    {   // fill T = (x + agg1)^T for 32 nodes
        int n = tid >> 2;
        long long node = n0 + n;
        int f0 = (tid & 3) * 16;
        if (node < N) {
            const float4* xp = (const float4*)(x + node * Hd);
            const float4* ap = (const float4*)(g_agg1 + node * Hd);
            #pragma unroll
            for (int c = 0; c < 4; c++) {
                float4 xv = xp[f0 / 4 + c];
                float4 av = ap[f0 / 4 + c];
                T[(f0 + 4 * c + 0) * NT + n] = xv.x + av.x;
                T[(f0 + 4 * c + 1) * NT + n] = xv.y + av.y;
                T[(f0 + 4 * c + 2) * NT + n] = xv.z + av.z;
                T[(f0 + 4 * c + 3) * NT + n] = xv.w + av.w;
            }
        } else {
            #pragma unroll
            for (int c = 0; c < 16; c++) T[(f0 + c) * NT + n] = 0.f;
        }
    }
    __syncthreads();

    int ng = tid & 7;     // node group: nodes ng*4 .. ng*4+3
    int jg = tid >> 3;    // out group : outs  jg*4 .. jg*4+3

    // acc2[n][p] = packed f32x2 accumulator for outputs (jg*4+2p, jg*4+2p+1)
    unsigned long long acc2[4][2];
    #pragma unroll
    for (int a = 0; a < 4; a++) { acc2[a][0] = 0ull; acc2[a][1] = 0ull; }

    #pragma unroll
    for (int k = 0; k < Hd; k++) {
        float4 tf = *(const float4*)&T[k * NT + ng * 4];
        ulonglong2 wv = *(const ulonglong2*)&sWa[k * Hd + jg * 4];
        unsigned long long t0, t1, t2, t3;
        PACK_DUP_F32X2(t0, tf.x);
        PACK_DUP_F32X2(t1, tf.y);
        PACK_DUP_F32X2(t2, tf.z);
        PACK_DUP_F32X2(t3, tf.w);
        FMA_F32X2(acc2[0][0], t0, wv.x, acc2[0][0]);
        FMA_F32X2(acc2[0][1], t0, wv.y, acc2[0][1]);
        FMA_F32X2(acc2[1][0], t1, wv.x, acc2[1][0]);
        FMA_F32X2(acc2[1][1], t1, wv.y, acc2[1][1]);
        FMA_F32X2(acc2[2][0], t2, wv.x, acc2[2][0]);
        FMA_F32X2(acc2[2][1], t2, wv.y, acc2[2][1]);
        FMA_F32X2(acc2[3][0], t3, wv.x, acc2[3][0]);
        FMA_F32X2(acc2[3][1], t3, wv.y, acc2[3][1]);
    }
    __syncthreads();

    // U[j][n] = relu(acc + ba)  (store into T)
    #pragma unroll
    for (int nn = 0; nn < 4; nn++) {
        #pragma unroll
        for (int p = 0; p < 2; p++) {
            unsigned lo, hi;
            asm("mov.b64 {%0, %1}, %2;" : "=r"(lo), "=r"(hi) : "l"(acc2[nn][p]));
            int j0 = jg * 4 + 2 * p;
            T[(j0 + 0) * NT + ng * 4 + nn] = fmaxf(__uint_as_float(lo) + sba[j0 + 0], 0.f);
            T[(j0 + 1) * NT + ng * 4 + nn] = fmaxf(__uint_as_float(hi) + sba[j0 + 1], 0.f);
        }
    }
    __syncthreads();

    #pragma unroll
    for (int a = 0; a < 4; a++) { acc2[a][0] = 0ull; acc2[a][1] = 0ull; }

    #pragma unroll
    for (int k = 0; k < Hd; k++) {
        float4 tf = *(const float4*)&T[k * NT + ng * 4];
        ulonglong2 wv = *(const ulonglong2*)&sWb[k * Hd + jg * 4];
        unsigned long long t0, t1, t2, t3;
        PACK_DUP_F32X2(t0, tf.x);
        PACK_DUP_F32X2(t1, tf.y);
        PACK_DUP_F32X2(t2, tf.z);
        PACK_DUP_F32X2(t3, tf.w);
        FMA_F32X2(acc2[0][0], t0, wv.x, acc2[0][0]);
        FMA_F32X2(acc2[0][1], t0, wv.y, acc2[0][1]);
        FMA_F32X2(acc2[1][0], t1, wv.x, acc2[1][0]);
        FMA_F32X2(acc2[1][1], t1, wv.y, acc2[1][1]);
        FMA_F32X2(acc2[2][0], t2, wv.x, acc2[2][0]);
        FMA_F32X2(acc2[2][1], t2, wv.y, acc2[2][1]);
        FMA_F32X2(acc2[3][0], t3, wv.x, acc2[3][0]);
        FMA_F32X2(acc2[3][1], t3, wv.y, acc2[3][1]);
    }

    // h1 = relu(conv1 output)
    #pragma unroll
    for (int nn = 0; nn < 4; nn++) {
        long long node = n0 + ng * 4 + nn;
        if (node < N) {
            float o[4];
            #pragma unroll
            for (int p = 0; p < 2; p++) {
                unsigned lo, hi;
                asm("mov.b64 {%0, %1}, %2;" : "=r"(lo), "=r"(hi) : "l"(acc2[nn][p]));
                o[2 * p + 0] = fmaxf(__uint_as_float(lo) + sbb[jg * 4 + 2 * p + 0], 0.f);
                o[2 * p + 1] = fmaxf(__uint_as_float(hi) + sbb[jg * 4 + 2 * p + 1], 0.f);
            }
            *(float4*)&g_h1[node * Hd + jg * 4] = make_float4(o[0], o[1], o[2], o[3]);
        }
    }
}

// ---------------- edge pass 2: only the pre-filtered edge list -------------
__global__ void k_edge2c(const void* __restrict__ ei, const float* __restrict__ ea,
                         const float* __restrict__ We2, const float* __restrict__ be2,
                         int E, int K) {
    __shared__ int tg[2 + MAXK];
    __shared__ float w[Hd], b[Hd];
    if (threadIdx.x < 2 + MAXK) tg[threadIdx.x] = g_targets[threadIdx.x];
    if (threadIdx.x < Hd) { w[threadIdx.x] = We2[threadIdx.x]; b[threadIdx.x] = be2[threadIdx.x]; }
    __syncthreads();

    int count = g_ecount;
    int is64 = g_is64;
    for (int idx = blockIdx.x * blockDim.x + threadIdx.x; idx < count;
         idx += gridDim.x * blockDim.x) {
        int e = g_elist[idx];
        int d;
        long long s;
        if (is64) {
            s = ((const long long*)ei)[e];
            d = (int)((const long long*)ei)[E + e];
        } else {
            s = (long long)((const int*)ei)[e];
            d = ((const int*)ei)[E + e];
        }
        unsigned mask = 0;
        #pragma unroll
        for (int t = 0; t < 2 + MAXK; t++)
            mask |= (d == tg[t]) ? (1u << t) : 0u;

        float a = ea[e];
        const float4* xs = (const float4*)(g_h1 + s * Hd);
        float4 m[Hd / 4];
        #pragma unroll
        for (int i = 0; i < Hd / 4; i++) {
            float4 xv = xs[i];
            float4 wv = ((const float4*)w)[i];
            float4 bv = ((const float4*)b)[i];
            m[i].x = fmaxf(xv.x + fmaf(a, wv.x, bv.x), 0.f);
            m[i].y = fmaxf(xv.y + fmaf(a, wv.y, bv.y), 0.f);
            m[i].z = fmaxf(xv.z + fmaf(a, wv.z, bv.z), 0.f);
            m[i].w = fmaxf(xv.w + fmaf(a, wv.w, bv.w), 0.f);
        }
        while (mask) {
            int t = __ffs(mask) - 1;
            mask &= mask - 1;
            float* base = &g_agg2[t * Hd];
            #pragma unroll
            for (int i = 0; i < Hd / 4; i++) {
                asm volatile("red.global.add.v4.f32 [%0], {%1,%2,%3,%4};"
                             :: "l"(base + 4 * i), "f"(m[i].x), "f"(m[i].y),
                                "f"(m[i].z), "f"(m[i].w)
                             : "memory");
            }
        }
    }
}

// ---------------- layer-2 MLP at 18 targets + Q head ----------------
__global__ void __launch_bounds__(256) k_final(
        const float* __restrict__ W2a, const float* __restrict__ b2a,
        const float* __restrict__ W2b, const float* __restrict__ b2b,
        const float* __restrict__ Wl1, const float* __restrict__ bl1,
        const float* __restrict__ Wl2, const float* __restrict__ bl2,
        float* __restrict__ out, int K) {
    __shared__ float sT[(2 + MAXK) * Hd];
    __shared__ float sU[(2 + MAXK) * Hd];
    __shared__ float sH2[(2 + MAXK) * Hd];
    __shared__ float sZ[MAXK * Hd];
    int tid = threadIdx.x;
    int nt = 2 + K;

    for (int i = tid; i < nt * Hd; i += 256) {
        int slot = i >> 6, j = i & 63;
        sT[i] = g_h1[(long long)g_targets[slot] * Hd + j] + g_agg2[i];
    }
    __syncthreads();

    for (int i = tid; i < nt * Hd; i += 256) {
        int slot = i >> 6, j = i & 63;
        float acc = b2a[j];
        const float* t = &sT[slot * Hd];
        #pragma unroll 8
        for (int k = 0; k < Hd; k++) acc = fmaf(t[k], __ldg(&W2a[k * Hd + j]), acc);
        sU[i] = fmaxf(acc, 0.f);
    }
    __syncthreads();

    for (int i = tid; i < nt * Hd; i += 256) {
        int slot = i >> 6, j = i & 63;
        float acc = b2b[j];
        const float* u = &sU[slot * Hd];
        #pragma unroll 8
        for (int k = 0; k < Hd; k++) acc = fmaf(u[k], __ldg(&W2b[k * Hd + j]), acc);
        sH2[i] = acc;   // no relu after conv2
    }
    __syncthreads();

    for (int i = tid; i < K * Hd; i += 256) {
        int k = i >> 6, j = i & 63;
        float acc = bl1[j];
        #pragma unroll 8
        for (int t = 0; t < Hd; t++)
            acc = fmaf(sH2[0 * Hd + t], __ldg(&Wl1[t * Hd + j]), acc);
        #pragma unroll 8
        for (int t = 0; t < Hd; t++)
            acc = fmaf(sH2[1 * Hd + t], __ldg(&Wl1[(Hd + t) * Hd + j]), acc);
        const float* nb = &sH2[(2 + k) * Hd];
        #pragma unroll 8
        for (int t = 0; t < Hd; t++)
            acc = fmaf(nb[t], __ldg(&Wl1[(2 * Hd + t) * Hd + j]), acc);
        sZ[i] = fmaxf(acc, 0.f);
    }
    __syncthreads();

    if (tid < K) {
        float acc = bl2[0];
        #pragma unroll 8
        for (int j = 0; j < Hd; j++) acc = fmaf(sZ[tid * Hd + j], Wl2[j], acc);
        out[tid] = acc;
    }
}

// ---------------- launcher ----------------
extern "C" void kernel_launch(void* const* d_in, const int* in_sizes, int n_in,
                              void* d_out, int out_size) {
    const float* x    = (const float*)d_in[0];
    const void*  ei   = d_in[1];
    const void*  curr = d_in[2];
    const void*  dest = d_in[3];
    const void*  nbr  = d_in[4];
    const float* ea   = (const float*)d_in[5];
    const float* We1  = (const float*)d_in[6];
    const float* be1  = (const float*)d_in[7];
    const float* W1a  = (const float*)d_in[8];
    const float* b1a  = (const float*)d_in[9];
    const float* W1b  = (const float*)d_in[10];
    const float* b1b  = (const float*)d_in[11];
    const float* We2  = (const float*)d_in[12];
    const float* be2  = (const float*)d_in[13];
    const float* W2a  = (const float*)d_in[14];
    const float* b2a  = (const float*)d_in[15];
    const float* W2b  = (const float*)d_in[16];
    const float* b2b  = (const float*)d_in[17];
    const float* Wl1  = (const float*)d_in[18];
    const float* bl1  = (const float*)d_in[19];
    const float* Wl2  = (const float*)d_in[20];
    const float* bl2  = (const float*)d_in[21];

    int N = in_sizes[0] / Hd;
    int E = in_sizes[5];
    int K = in_sizes[4];
    if (K > MAXK) K = MAXK;

    int n4 = (N * Hd) / 4;
    k_prep<<<(n4 + 255) / 256, 256>>>(ei, E, (long long)N, curr, dest, nbr, K);

    {
        long long threads = (long long)E * 16;
        int blocks = (int)((threads + 255) / 256);
        k_edge1<<<blocks, 256>>>(x, ei, ea, We1, be1, E);
    }

    k_mlp1<<<(N + NT - 1) / NT, 128>>>(x, W1a, b1a, W1b, b1b, N);

    k_edge2c<<<64, 256>>>(ei, ea, We2, be2, E, K);

    k_final<<<1, 256>>>(W2a, b2a, W2b, b2b, Wl1, bl1, Wl2, bl2,
                        (float*)d_out, K);
}

// round 5
// speedup vs baseline: 2.1152x; 2.1152x over previous
#include <cuda_runtime.h>
#include <cuda_bf16.h>
#include <cstdint>

#define MAXN 50000
#define MAXE 800000
#define Hd   64
#define MAXK 16
#define NTGT (2 + MAXK)

// ---------------- device scratch (no allocs allowed) ----------------
static __device__ float    g_agg1[(size_t)MAXN * Hd]; // layer-1 agg (only S1 rows used)
static __device__ float    g_h1[(size_t)MAXN * Hd];   // relu(conv1 out) (only S1 rows)
static __device__ int      g_is64;
static __device__ int      g_targets[NTGT];           // [curr, dest, nbr0..15]
static __device__ float    g_agg2[NTGT * Hd];
static __device__ unsigned g_bitmap[(MAXN + 31) / 32];// membership of S1
static __device__ int      g_s1[MAXN];                // S1 node list
static __device__ int      g_ns1;
static __device__ int      g_elist1[MAXE];            // edges with dst in S1
static __device__ int      g_ne1;
static __device__ int      g_elist2[MAXE];            // edges with dst in targets
static __device__ int      g_ne2;

// ---------------- prep: detect dtype, zero bitmap/counters, load targets ----
__global__ void k_prep(const void* ei, int E, long long N,
                       const void* curr, const void* dest, const void* nbr, int K) {
    int tid = threadIdx.x;
    if (tid == 0) {
        const long long* p = (const long long*)ei;
        int n = E < 8 ? E : 8;
        int ok = 1;
        for (int q = 0; q < n; q++) {
            long long v = p[q];
            if (v < 0 || v >= N) { ok = 0; break; }
        }
        g_is64 = ok;
        g_ne1 = 0; g_ne2 = 0; g_ns1 = 0;
    }
    __syncthreads();
    int is64 = g_is64;

    for (int i = tid; i < (MAXN + 31) / 32; i += blockDim.x) g_bitmap[i] = 0u;
    for (int i = tid; i < NTGT * Hd; i += blockDim.x) g_agg2[i] = 0.f;

    if (tid < NTGT) {
        int v = -1;
        if (tid == 0)       v = is64 ? (int)((const long long*)curr)[0] : ((const int*)curr)[0];
        else if (tid == 1)  v = is64 ? (int)((const long long*)dest)[0] : ((const int*)dest)[0];
        else if (tid < 2 + K)
            v = is64 ? (int)((const long long*)nbr)[tid - 2] : ((const int*)nbr)[tid - 2];
        g_targets[tid] = v;
    }
    __syncthreads();

    // seed S1 with the targets (dedup via bitmap)
    if (tid < 2 + K) {
        int v = g_targets[tid];
        unsigned bit = 1u << (v & 31);
        unsigned old = atomicOr(&g_bitmap[v >> 5], bit);
        if (!(old & bit)) { int sl = atomicAdd(&g_ns1, 1); g_s1[sl] = v; }
    }
}

// ---------------- scan A: find edges with dst in targets; grow S1 by src ----
__global__ void k_scanA(const void* __restrict__ ei, int E) {
    __shared__ int tg[NTGT];
    if (threadIdx.x < NTGT) tg[threadIdx.x] = g_targets[threadIdx.x];
    __syncthreads();

    int e = blockIdx.x * blockDim.x + threadIdx.x;
    if (e >= E) return;
    int is64 = g_is64;
    int d = is64 ? (int)((const long long*)ei)[E + e] : ((const int*)ei)[E + e];

    bool match = false;
    #pragma unroll
    for (int t = 0; t < NTGT; t++) match |= (d == tg[t]);
    if (!match) return;

    int pos = atomicAdd(&g_ne2, 1);
    g_elist2[pos] = e;

    int s = is64 ? (int)((const long long*)ei)[e] : ((const int*)ei)[e];
    unsigned bit = 1u << (s & 31);
    unsigned old = atomicOr(&g_bitmap[s >> 5], bit);
    if (!(old & bit)) { int sl = atomicAdd(&g_ns1, 1); g_s1[sl] = s; }
}

// ---------------- scan B: zero S1 agg rows; find edges with dst in S1 ------
__global__ void k_scanB(const void* __restrict__ ei, int E) {
    int gid = blockIdx.x * blockDim.x + threadIdx.x;
    int stride = gridDim.x * blockDim.x;

    int ns1 = g_ns1;
    for (int i = gid; i < ns1 * 16; i += stride) {
        size_t row = (size_t)g_s1[i >> 4];
        ((float4*)(g_agg1 + row * Hd))[i & 15] = make_float4(0.f, 0.f, 0.f, 0.f);
    }

    if (gid < E) {
        int is64 = g_is64;
        int d = is64 ? (int)((const long long*)ei)[E + gid] : ((const int*)ei)[E + gid];
        if ((g_bitmap[d >> 5] >> (d & 31)) & 1u) {
            int pos = atomicAdd(&g_ne1, 1);
            g_elist1[pos] = gid;
        }
    }
}

// ---------------- edge pass 1 (sparse): scatter-add msgs into agg1 ---------
__global__ void k_edge1s(const float* __restrict__ x, const void* __restrict__ ei,
                         const float* __restrict__ ea, const float* __restrict__ We1,
                         const float* __restrict__ be1, int E) {
    int total = g_ne1 * 16;
    int is64 = g_is64;
    for (int idx = blockIdx.x * blockDim.x + threadIdx.x; idx < total;
         idx += gridDim.x * blockDim.x) {
        int e = g_elist1[idx >> 4];
        int l = idx & 15;
        long long s, d;
        if (is64) {
            const long long* p = (const long long*)ei;
            s = p[e]; d = p[E + e];
        } else {
            const int* p = (const int*)ei;
            s = (long long)p[e]; d = (long long)p[E + e];
        }
        float a = __ldg(&ea[e]);
        float4 xv = __ldg((const float4*)(x + s * Hd) + l);
        float4 wv = __ldg((const float4*)We1 + l);
        float4 bv = __ldg((const float4*)be1 + l);
        float4 m;
        m.x = fmaxf(xv.x + fmaf(a, wv.x, bv.x), 0.f);
        m.y = fmaxf(xv.y + fmaf(a, wv.y, bv.y), 0.f);
        m.z = fmaxf(xv.z + fmaf(a, wv.z, bv.z), 0.f);
        m.w = fmaxf(xv.w + fmaf(a, wv.w, bv.w), 0.f);
        float* dp = g_agg1 + d * Hd + l * 4;
        asm volatile("red.global.add.v4.f32 [%0], {%1,%2,%3,%4};"
                     :: "l"(dp), "f"(m.x), "f"(m.y), "f"(m.z), "f"(m.w)
                     : "memory");
    }
}

// ---------------- node MLP for layer 1 at S1 nodes only --------------------
// 32 nodes / block-iter, 128 threads, two 64x64 GEMMs, 4x4 microtile.
#define NT 32
__global__ void __launch_bounds__(128) k_mlp1s(
        const float* __restrict__ x,
        const float* __restrict__ Wa, const float* __restrict__ ba,
        const float* __restrict__ Wb, const float* __restrict__ bb) {
    int ns1 = g_ns1;
    if ((long long)blockIdx.x * NT >= ns1) return;

    __shared__ float sWa[Hd * Hd];
    __shared__ float sWb[Hd * Hd];
    __shared__ float sba[Hd], sbb[Hd];
    __shared__ float T[Hd * NT];

    int tid = threadIdx.x;
    for (int i = tid * 4; i < Hd * Hd; i += 128 * 4) {
        *(float4*)&sWa[i] = *(const float4*)&Wa[i];
        *(float4*)&sWb[i] = *(const float4*)&Wb[i];
    }
    if (tid < Hd) { sba[tid] = ba[tid]; sbb[tid] = bb[tid]; }

    int ng = tid & 7;
    int jg = tid >> 3;

    for (int base = blockIdx.x * NT; base < ns1; base += gridDim.x * NT) {
        __syncthreads();   // protect T from previous iteration readers
        {   // fill T = (x + agg1)^T for 32 S1 nodes
            int n = tid >> 2;
            int idx = base + n;
            int f0 = (tid & 3) * 16;
            if (idx < ns1) {
                size_t node = (size_t)g_s1[idx];
                const float4* xp = (const float4*)(x + node * Hd);
                const float4* ap = (const float4*)(g_agg1 + node * Hd);
                #pragma unroll
                for (int c = 0; c < 4; c++) {
                    float4 xv = xp[f0 / 4 + c];
                    float4 av = ap[f0 / 4 + c];
                    T[(f0 + 4 * c + 0) * NT + n] = xv.x + av.x;
                    T[(f0 + 4 * c + 1) * NT + n] = xv.y + av.y;
                    T[(f0 + 4 * c + 2) * NT + n] = xv.z + av.z;
                    T[(f0 + 4 * c + 3) * NT + n] = xv.w + av.w;
                }
            } else {
                #pragma unroll
                for (int c = 0; c < 16; c++) T[(f0 + c) * NT + n] = 0.f;
            }
        }
        __syncthreads();

        float acc[4][4];
        #pragma unroll
        for (int a = 0; a < 4; a++)
            #pragma unroll
            for (int b = 0; b < 4; b++) acc[a][b] = 0.f;

        #pragma unroll
        for (int k = 0; k < Hd; k++) {
            float4 tf = *(const float4*)&T[k * NT + ng * 4];
            float4 wf = *(const float4*)&sWa[k * Hd + jg * 4];
            float tv[4] = {tf.x, tf.y, tf.z, tf.w};
            float wv[4] = {wf.x, wf.y, wf.z, wf.w};
            #pragma unroll
            for (int nn = 0; nn < 4; nn++)
                #pragma unroll
                for (int jj = 0; jj < 4; jj++)
                    acc[nn][jj] = fmaf(tv[nn], wv[jj], acc[nn][jj]);
        }
        __syncthreads();

        #pragma unroll
        for (int jj = 0; jj < 4; jj++) {
            float bv = sba[jg * 4 + jj];
            #pragma unroll
            for (int nn = 0; nn < 4; nn++)
                T[(jg * 4 + jj) * NT + ng * 4 + nn] = fmaxf(acc[nn][jj] + bv, 0.f);
        }
        __syncthreads();

        #pragma unroll
        for (int a = 0; a < 4; a++)
            #pragma unroll
            for (int b = 0; b < 4; b++) acc[a][b] = 0.f;

        #pragma unroll
        for (int k = 0; k < Hd; k++) {
            float4 tf = *(const float4*)&T[k * NT + ng * 4];
            float4 wf = *(const float4*)&sWb[k * Hd + jg * 4];
            float tv[4] = {tf.x, tf.y, tf.z, tf.w};
            float wv[4] = {wf.x, wf.y, wf.z, wf.w};
            #pragma unroll
            for (int nn = 0; nn < 4; nn++)
                #pragma unroll
                for (int jj = 0; jj < 4; jj++)
                    acc[nn][jj] = fmaf(tv[nn], wv[jj], acc[nn][jj]);
        }

        #pragma unroll
        for (int nn = 0; nn < 4; nn++) {
            int idx = base + ng * 4 + nn;
            if (idx < ns1) {
                size_t node = (size_t)g_s1[idx];
                float4 o;
                o.x = fmaxf(acc[nn][0] + sbb[jg * 4 + 0], 0.f);
                o.y = fmaxf(acc[nn][1] + sbb[jg * 4 + 1], 0.f);
                o.z = fmaxf(acc[nn][2] + sbb[jg * 4 + 2], 0.f);
                o.w = fmaxf(acc[nn][3] + sbb[jg * 4 + 3], 0.f);
                *(float4*)&g_h1[node * Hd + jg * 4] = o;
            }
        }
    }
}

// ---------------- edge pass 2: the pre-filtered target-edge list -----------
__global__ void k_edge2c(const void* __restrict__ ei, const float* __restrict__ ea,
                         const float* __restrict__ We2, const float* __restrict__ be2,
                         int E, int K) {
    __shared__ int tg[NTGT];
    __shared__ float w[Hd], b[Hd];
    if (threadIdx.x < NTGT) tg[threadIdx.x] = g_targets[threadIdx.x];
    if (threadIdx.x < Hd) { w[threadIdx.x] = We2[threadIdx.x]; b[threadIdx.x] = be2[threadIdx.x]; }
    __syncthreads();

    int count = g_ne2;
    int is64 = g_is64;
    for (int idx = blockIdx.x * blockDim.x + threadIdx.x; idx < count;
         idx += gridDim.x * blockDim.x) {
        int e = g_elist2[idx];
        int d;
        long long s;
        if (is64) {
            s = ((const long long*)ei)[e];
            d = (int)((const long long*)ei)[E + e];
        } else {
            s = (long long)((const int*)ei)[e];
            d = ((const int*)ei)[E + e];
        }
        unsigned mask = 0;
        #pragma unroll
        for (int t = 0; t < NTGT; t++)
            mask |= (d == tg[t]) ? (1u << t) : 0u;

        float a = ea[e];
        const float4* xs = (const float4*)(g_h1 + s * Hd);
        float4 m[Hd / 4];
        #pragma unroll
        for (int i = 0; i < Hd / 4; i++) {
            float4 xv = xs[i];
            float4 wv = ((const float4*)w)[i];
            float4 bv = ((const float4*)b)[i];
            m[i].x = fmaxf(xv.x + fmaf(a, wv.x, bv.x), 0.f);
            m[i].y = fmaxf(xv.y + fmaf(a, wv.y, bv.y), 0.f);
            m[i].z = fmaxf(xv.z + fmaf(a, wv.z, bv.z), 0.f);
            m[i].w = fmaxf(xv.w + fmaf(a, wv.w, bv.w), 0.f);
        }
        while (mask) {
            int t = __ffs(mask) - 1;
            mask &= mask - 1;
            float* base = &g_agg2[t * Hd];
            #pragma unroll
            for (int i = 0; i < Hd / 4; i++) {
                asm volatile("red.global.add.v4.f32 [%0], {%1,%2,%3,%4};"
                             :: "l"(base + 4 * i), "f"(m[i].x), "f"(m[i].y),
                                "f"(m[i].z), "f"(m[i].w)
                             : "memory");
            }
        }
    }
}

// ---------------- layer-2 MLP at 18 targets + Q head ----------------
__global__ void __launch_bounds__(256) k_final(
        const float* __restrict__ W2a, const float* __restrict__ b2a,
        const float* __restrict__ W2b, const float* __restrict__ b2b,
        const float* __restrict__ Wl1, const float* __restrict__ bl1,
        const float* __restrict__ Wl2, const float* __restrict__ bl2,
        float* __restrict__ out, int K) {
    __shared__ float sT[NTGT * Hd];
    __shared__ float sU[NTGT * Hd];
    __shared__ float sH2[NTGT * Hd];
    __shared__ float sZ[MAXK * Hd];
    int tid = threadIdx.x;
    int nt = 2 + K;

    for (int i = tid; i < nt * Hd; i += 256) {
        int slot = i >> 6, j = i & 63;
        sT[i] = g_h1[(size_t)g_targets[slot] * Hd + j] + g_agg2[i];
    }
    __syncthreads();

    for (int i = tid; i < nt * Hd; i += 256) {
        int slot = i >> 6, j = i & 63;
        float acc = b2a[j];
        const float* t = &sT[slot * Hd];
        #pragma unroll 8
        for (int k = 0; k < Hd; k++) acc = fmaf(t[k], __ldg(&W2a[k * Hd + j]), acc);
        sU[i] = fmaxf(acc, 0.f);
    }
    __syncthreads();

    for (int i = tid; i < nt * Hd; i += 256) {
        int slot = i >> 6, j = i & 63;
        float acc = b2b[j];
        const float* u = &sU[slot * Hd];
        #pragma unroll 8
        for (int k = 0; k < Hd; k++) acc = fmaf(u[k], __ldg(&W2b[k * Hd + j]), acc);
        sH2[i] = acc;   // no relu after conv2
    }
    __syncthreads();

    for (int i = tid; i < K * Hd; i += 256) {
        int k = i >> 6, j = i & 63;
        float acc = bl1[j];
        #pragma unroll 8
        for (int t = 0; t < Hd; t++)
            acc = fmaf(sH2[0 * Hd + t], __ldg(&Wl1[t * Hd + j]), acc);
        #pragma unroll 8
        for (int t = 0; t < Hd; t++)
            acc = fmaf(sH2[1 * Hd + t], __ldg(&Wl1[(Hd + t) * Hd + j]), acc);
        const float* nb = &sH2[(2 + k) * Hd];
        #pragma unroll 8
        for (int t = 0; t < Hd; t++)
            acc = fmaf(nb[t], __ldg(&Wl1[(2 * Hd + t) * Hd + j]), acc);
        sZ[i] = fmaxf(acc, 0.f);
    }
    __syncthreads();

    if (tid < K) {
        float acc = bl2[0];
        #pragma unroll 8
        for (int j = 0; j < Hd; j++) acc = fmaf(sZ[tid * Hd + j], Wl2[j], acc);
        out[tid] = acc;
    }
}

// ---------------- launcher ----------------
extern "C" void kernel_launch(void* const* d_in, const int* in_sizes, int n_in,
                              void* d_out, int out_size) {
    const float* x    = (const float*)d_in[0];
    const void*  ei   = d_in[1];
    const void*  curr = d_in[2];
    const void*  dest = d_in[3];
    const void*  nbr  = d_in[4];
    const float* ea   = (const float*)d_in[5];
    const float* We1  = (const float*)d_in[6];
    const float* be1  = (const float*)d_in[7];
    const float* W1a  = (const float*)d_in[8];
    const float* b1a  = (const float*)d_in[9];
    const float* W1b  = (const float*)d_in[10];
    const float* b1b  = (const float*)d_in[11];
    const float* We2  = (const float*)d_in[12];
    const float* be2  = (const float*)d_in[13];
    const float* W2a  = (const float*)d_in[14];
    const float* b2a  = (const float*)d_in[15];
    const float* W2b  = (const float*)d_in[16];
    const float* b2b  = (const float*)d_in[17];
    const float* Wl1  = (const float*)d_in[18];
    const float* bl1  = (const float*)d_in[19];
    const float* Wl2  = (const float*)d_in[20];
    const float* bl2  = (const float*)d_in[21];

    int N = in_sizes[0] / Hd;
    int E = in_sizes[5];
    int K = in_sizes[4];
    if (K > MAXK) K = MAXK;

    k_prep<<<1, 256>>>(ei, E, (long long)N, curr, dest, nbr, K);
    k_scanA<<<(E + 255) / 256, 256>>>(ei, E);
    k_scanB<<<(E + 255) / 256, 256>>>(ei, E);
    k_edge1s<<<256, 256>>>(x, ei, ea, We1, be1, E);
    k_mlp1s<<<160, 128>>>(x, W1a, b1a, W1b, b1b);
    k_edge2c<<<32, 256>>>(ei, ea, We2, be2, E, K);
    k_final<<<1, 256>>>(W2a, b2a, W2b, b2b, Wl1, bl1, Wl2, bl2,
                        (float*)d_out, K);
}